// round 12
// baseline (speedup 1.0000x reference)
#include <cuda_runtime.h>

// B3-spline undecimated wavelet transform (a trous), 3 levels, fully fused.
// x: (8, 1024, 1024) f32 -> out: (8, 4, 1024, 1024) f32 = [w1, w2, w3, c3]
//
// R12: full-Q ping-pong (7 phases, large per-phase item pools -> low barrier
// quantization waste) at 1024 threads x 2 CTAs/SM = 64 warps/SM. Last level
// emits w3 + c3 directly (no P writeback, no epilogue). Vectorized interior
// halo load.

#define IMG   1024
#define TS    64
#define HL    14
#define S     (TS + 2*HL)   // 92
#define SP    96            // row stride (16B-aligned rows)
#define NTHR  1024
#define SHIFT 2             // phys col = logical col + SHIFT

#define SMEM_FLOATS (2 * S * SP + 8)
#define SMEM_BYTES  (SMEM_FLOATS * sizeof(float))   // 70688 B

__device__ __forceinline__ int reflect_idx(int g) {
    if (g < 0) g = -g;
    if (g >= IMG) g = 2 * IMG - 2 - g;
    return g;
}

__device__ __forceinline__ float4 f4_add(float4 a, float4 b) {
    return make_float4(a.x + b.x, a.y + b.y, a.z + b.z, a.w + b.w);
}

template<int d, int h, int a, bool LAST>
__device__ __forceinline__ void do_level(float* __restrict__ P,
                                         float* __restrict__ Q,
                                         float* __restrict__ wch,
                                         float* __restrict__ cch,
                                         int ty0, int tx0) {
    const float w0 = 0.0625f, w1 = 0.25f, w2 = 0.375f;

    // ---- H-conv (vertical): P -> Q. rows [a, S-a), cols [h, S-h).
    //      8-row strips, 1 col/thread, conflict-free scalar LDS/STS.
    {
        constexpr int rows   = S - 2 * a;      // 88 / 80 / 64
        constexpr int cols   = S - 2 * h;      // 92 / 88 / 80
        constexpr int strips = rows / 8;       // 11 / 10 / 8
        constexpr int nw     = 8 + 4 * d;      // 12 / 16 / 24
        for (int idx = threadIdx.x; idx < strips * cols; idx += NTHR) {
            int x  = idx % cols;
            int t  = idx / cols;
            int y0 = a + 8 * t;
            int oc = h + x + SHIFT;
            int ob = (y0 - 2 * d) * SP + oc;
            float v[nw];
#pragma unroll
            for (int i = 0; i < nw; i++) v[i] = P[ob + i * SP];
#pragma unroll
            for (int i = 0; i < 8; i++) {
                Q[(y0 + i) * SP + oc] = w2 * v[2 * d + i]
                                      + w1 * (v[d + i] + v[3 * d + i])
                                      + w0 * (v[i] + v[4 * d + i]);
            }
        }
    }
    __syncthreads();

    // ---- W-conv (horizontal): Q -> P in place (unless LAST), emit w on
    //      center (and c3 if LAST). 4-col float4 groups (lanes 16B apart).
    {
        constexpr int n2  = S - 2 * a;                     // 88 / 80 / 64
        constexpr int xg  = n2 / 4;                        // 22 / 20 / 16
        for (int idx = threadIdx.x; idx < n2 * xg; idx += NTHR) {
            int g  = idx % xg;
            int y  = a + idx / xg;
            int x0 = a + 4 * g;                 // logical
            int op = y * SP + x0 + SHIFT;       // phys, 16B-aligned
            float c0, c1, c2, c3;
            if constexpr (d == 4) {
                // taps land exactly on float4 lanes
                float4 A = *reinterpret_cast<const float4*>(&Q[op - 8]);
                float4 B = *reinterpret_cast<const float4*>(&Q[op - 4]);
                float4 C = *reinterpret_cast<const float4*>(&Q[op]);
                float4 D = *reinterpret_cast<const float4*>(&Q[op + 4]);
                float4 E = *reinterpret_cast<const float4*>(&Q[op + 8]);
                float4 AE = f4_add(A, E), BD = f4_add(B, D);
                c0 = w0 * AE.x + w1 * BD.x + w2 * C.x;
                c1 = w0 * AE.y + w1 * BD.y + w2 * C.y;
                c2 = w0 * AE.z + w1 * BD.z + w2 * C.z;
                c3 = w0 * AE.w + w1 * BD.w + w2 * C.w;
            } else {
                constexpr int off = ((a - 2 * d) + SHIFT) & 3;   // 2 (d=1), 0 (d=2)
                constexpr int nw  = (4 * d + 4 + off + 3) & ~3;  // 12 / 12
                int ow = op - 2 * d - off;                        // 16B-aligned
                float v[nw];
#pragma unroll
                for (int k = 0; k < nw / 4; k++) {
                    float4 t4 = *reinterpret_cast<const float4*>(&Q[ow + 4 * k]);
                    v[4 * k] = t4.x; v[4 * k + 1] = t4.y;
                    v[4 * k + 2] = t4.z; v[4 * k + 3] = t4.w;
                }
                c0 = w2 * v[off + 2 * d]     + w1 * (v[off + d]     + v[off + 3 * d])
                   + w0 * (v[off]            + v[off + 4 * d]);
                c1 = w2 * v[off + 2 * d + 1] + w1 * (v[off + d + 1] + v[off + 3 * d + 1])
                   + w0 * (v[off + 1]        + v[off + 4 * d + 1]);
                c2 = w2 * v[off + 2 * d + 2] + w1 * (v[off + d + 2] + v[off + 3 * d + 2])
                   + w0 * (v[off + 2]        + v[off + 4 * d + 2]);
                c3 = w2 * v[off + 2 * d + 3] + w1 * (v[off + d + 3] + v[off + 3 * d + 3])
                   + w0 * (v[off + 3]        + v[off + 4 * d + 3]);
            }
            float4 prev = *reinterpret_cast<const float4*>(&P[op]);
            if constexpr (!LAST)
                *reinterpret_cast<float4*>(&P[op]) = make_float4(c0, c1, c2, c3);
            bool center = (a == HL) ||
                          (y >= HL && y < S - HL && x0 >= HL && x0 < S - HL);
            if (center) {
                int gy = ty0 + y - HL;
                int gx = tx0 + x0 - HL;
                *reinterpret_cast<float4*>(&wch[gy * IMG + gx]) =
                    make_float4(prev.x - c0, prev.y - c1, prev.z - c2, prev.w - c3);
                if constexpr (LAST)
                    *reinterpret_cast<float4*>(&cch[gy * IMG + gx]) =
                        make_float4(c0, c1, c2, c3);
            }
        }
    }
    __syncthreads();
}

__global__ void __launch_bounds__(NTHR, 2) uwt_kernel(const float* __restrict__ x,
                                                      float* __restrict__ out) {
    extern __shared__ float smem[];
    float* P = smem;
    float* Q = smem + S * SP + 4;

    const int b   = blockIdx.z;
    const int ty0 = blockIdx.y * TS;
    const int tx0 = blockIdx.x * TS;
    const float* xb = x + (size_t)b * IMG * IMG;

    // ---- load c0 with halo ----
    const bool interior = (tx0 >= 64 && tx0 <= IMG - TS - 16) &&
                          (ty0 >= 64 && ty0 <= IMG - TS - 16);
    if (interior) {
        // full 96-wide rows (logical cols [-2, 94)), 16B-aligned LDG/STS.128
        const float* src = xb + (size_t)(ty0 - HL) * IMG + (tx0 - 16);
        for (int idx = threadIdx.x; idx < S * (SP / 4); idx += NTHR) {
            int ly = idx / (SP / 4);
            int k  = idx - ly * (SP / 4);
            float4 v4 = *reinterpret_cast<const float4*>(src + (size_t)ly * IMG + 4 * k);
            *reinterpret_cast<float4*>(&P[ly * SP + 4 * k]) = v4;
        }
    } else {
        for (int idx = threadIdx.x; idx < S * S; idx += NTHR) {
            int ly = idx / S;
            int lx = idx - ly * S;
            int gy = reflect_idx(ty0 + ly - HL);
            int gx = reflect_idx(tx0 + lx - HL);
            P[ly * SP + lx + SHIFT] = xb[gy * IMG + gx];
        }
    }
    __syncthreads();

    float* ob = out + (size_t)b * 4 * IMG * IMG;
    do_level<1, 0, 2, false>(P, Q, ob + 0 * IMG * IMG, nullptr, ty0, tx0);
    do_level<2, 2, 6, false>(P, Q, ob + 1 * IMG * IMG, nullptr, ty0, tx0);
    do_level<4, 6, 14, true>(P, Q, ob + 2 * IMG * IMG, ob + 3 * IMG * IMG,
                             ty0, tx0);
}

extern "C" void kernel_launch(void* const* d_in, const int* in_sizes, int n_in,
                              void* d_out, int out_size) {
    const float* x = (const float*)d_in[0];
    float* out     = (float*)d_out;

    cudaFuncSetAttribute(uwt_kernel, cudaFuncAttributeMaxDynamicSharedMemorySize,
                         (int)SMEM_BYTES);

    dim3 grid(IMG / TS, IMG / TS, 8);
    uwt_kernel<<<grid, NTHR, SMEM_BYTES>>>(x, out);
}

// round 13
// speedup vs baseline: 1.1816x; 1.1816x over previous
#include <cuda_runtime.h>

// B3-spline undecimated wavelet transform (a trous), 3 levels, fully fused.
// x: (8, 1024, 1024) f32 -> out: (8, 4, 1024, 1024) f32 = [w1, w2, w3, c3]
//
// R13: no halo phase. Level-1 vertical conv (H1) reads gmem directly
// (coalesced vertical windows); W1 reads prev=c0 from gmem (center only).
// Per-level Q column shift makes every W window exactly minimal float4 loads
// (2/3/5). Full-Q ping-pong, 5 barriers, 3 CTAs x 640 thr = 60 warps/SM.
// Level 3 emits w3 + c3 directly.

#define IMG   1024
#define TS    64
#define HL    14
#define S     (TS + 2*HL)   // 92
#define SP    96            // row stride (16B-aligned rows)
#define NTHR  640
#define SHIFT 2             // P phys col = logical col + SHIFT

#define SMEM_FLOATS (2 * S * SP + 8)
#define SMEM_BYTES  (SMEM_FLOATS * sizeof(float))   // 70688 B

__device__ __forceinline__ int reflect_idx(int g) {
    if (g < 0) g = -g;
    if (g >= IMG) g = 2 * IMG - 2 - g;
    return g;
}

// ---- H1: level-1 vertical conv, gmem -> Q (qs=0). rows [2,90), cols [0,92).
//      8-row strips; adjacent lanes = adjacent gmem cols (coalesced LDG).
template<bool REFL>
__device__ __forceinline__ void h1_pass(const float* __restrict__ xb,
                                        float* __restrict__ Q,
                                        int ty0, int tx0) {
    const float w0 = 0.0625f, w1 = 0.25f, w2 = 0.375f;
    constexpr int strips = 11, cols = 92;
    for (int idx = threadIdx.x; idx < strips * cols; idx += NTHR) {
        int x  = idx % cols;
        int t  = idx / cols;
        int y0 = 2 + 8 * t;
        float v[12];
        if (REFL) {
            int gx = reflect_idx(tx0 + x - HL);
#pragma unroll
            for (int i = 0; i < 12; i++) {
                int gy = reflect_idx(ty0 + y0 + i - 2 - HL);
                v[i] = xb[gy * IMG + gx];
            }
        } else {
            const float* src = xb + (size_t)(ty0 + y0 - 2 - HL) * IMG
                                  + (tx0 + x - HL);
#pragma unroll
            for (int i = 0; i < 12; i++) v[i] = src[(size_t)i * IMG];
        }
#pragma unroll
        for (int i = 0; i < 8; i++) {
            Q[(y0 + i) * SP + x] = w2 * v[2 + i]
                                 + w1 * (v[1 + i] + v[3 + i])
                                 + w0 * (v[i] + v[4 + i]);
        }
    }
}

// ---- W1: level-1 horizontal conv, Q(qs=0) -> P (c1), emit w1 = x - c1.
//      4-col groups; window exactly 8 floats = 2 aligned LDS.128.
__device__ __forceinline__ void w1_pass(float* __restrict__ P,
                                        const float* __restrict__ Q,
                                        const float* __restrict__ xb,
                                        float* __restrict__ wch,
                                        int ty0, int tx0) {
    const float w0 = 0.0625f, w1 = 0.25f, w2 = 0.375f;
    constexpr int n2 = 88, xg = 22;
    for (int idx = threadIdx.x; idx < n2 * xg; idx += NTHR) {
        int g  = idx % xg;
        int y  = 2 + idx / xg;
        int x0 = 2 + 4 * g;                 // logical
        int qw = y * SP + 4 * g;            // window start (logical x0-2, qs=0)
        float v[8];
        float4 t0 = *reinterpret_cast<const float4*>(&Q[qw]);
        float4 t1 = *reinterpret_cast<const float4*>(&Q[qw + 4]);
        v[0]=t0.x; v[1]=t0.y; v[2]=t0.z; v[3]=t0.w;
        v[4]=t1.x; v[5]=t1.y; v[6]=t1.z; v[7]=t1.w;
        float c0 = w2*v[2] + w1*(v[1]+v[3]) + w0*(v[0]+v[4]);
        float c1 = w2*v[3] + w1*(v[2]+v[4]) + w0*(v[1]+v[5]);
        float c2 = w2*v[4] + w1*(v[3]+v[5]) + w0*(v[2]+v[6]);
        float c3 = w2*v[5] + w1*(v[4]+v[6]) + w0*(v[3]+v[7]);
        int op = y * SP + x0 + SHIFT;
        *reinterpret_cast<float4*>(&P[op]) = make_float4(c0, c1, c2, c3);
        if (y >= HL && y < S - HL && x0 >= HL && x0 < S - HL) {
            int gy = ty0 + y - HL;
            int gx = tx0 + x0 - HL;
            float4 prev = *reinterpret_cast<const float4*>(&xb[(size_t)gy * IMG + gx]);
            *reinterpret_cast<float4*>(&wch[gy * IMG + gx]) =
                make_float4(prev.x - c0, prev.y - c1, prev.z - c2, prev.w - c3);
        }
    }
}

// ---- generic level (2, 3): H then W, Q at qs=SHIFT ----
template<int d, int h, int a, bool LAST>
__device__ __forceinline__ void do_level(float* __restrict__ P,
                                         float* __restrict__ Q,
                                         float* __restrict__ wch,
                                         float* __restrict__ cch,
                                         int ty0, int tx0) {
    const float w0 = 0.0625f, w1 = 0.25f, w2 = 0.375f;

    // H-conv (vertical): P -> Q. rows [a, S-a), cols [h, S-h). 8-row strips.
    {
        constexpr int rows   = S - 2 * a;      // 80 / 64
        constexpr int cols   = S - 2 * h;      // 88 / 80
        constexpr int strips = rows / 8;       // 10 / 8
        constexpr int nw     = 8 + 4 * d;      // 16 / 24
        for (int idx = threadIdx.x; idx < strips * cols; idx += NTHR) {
            int x  = idx % cols;
            int t  = idx / cols;
            int y0 = a + 8 * t;
            int oc = h + x + SHIFT;
            int ob = (y0 - 2 * d) * SP + oc;
            float v[nw];
#pragma unroll
            for (int i = 0; i < nw; i++) v[i] = P[ob + i * SP];
#pragma unroll
            for (int i = 0; i < 8; i++) {
                Q[(y0 + i) * SP + oc] = w2 * v[2 * d + i]
                                      + w1 * (v[d + i] + v[3 * d + i])
                                      + w0 * (v[i] + v[4 * d + i]);
            }
        }
    }
    __syncthreads();

    // W-conv (horizontal): Q -> P in place (unless LAST), emit w (and c3).
    // Window start (a - 2d + SHIFT) + 4g is 16B-aligned: loads are minimal.
    {
        constexpr int n2  = S - 2 * a;                  // 80 / 64
        constexpr int xg  = n2 / 4;                     // 20 / 16
        constexpr int nw  = 4 * d + 4;                  // 12 / 20
        static_assert(((a - 2 * d + SHIFT) & 3) == 0, "window alignment");
        for (int idx = threadIdx.x; idx < n2 * xg; idx += NTHR) {
            int g  = idx % xg;
            int y  = a + idx / xg;
            int x0 = a + 4 * g;                  // logical
            int ow = y * SP + (a - 2 * d + SHIFT) + 4 * g;
            float v[nw];
#pragma unroll
            for (int k = 0; k < nw / 4; k++) {
                float4 t4 = *reinterpret_cast<const float4*>(&Q[ow + 4 * k]);
                v[4 * k] = t4.x; v[4 * k + 1] = t4.y;
                v[4 * k + 2] = t4.z; v[4 * k + 3] = t4.w;
            }
            float c0 = w2*v[2*d]   + w1*(v[d]   + v[3*d])   + w0*(v[0] + v[4*d]);
            float c1 = w2*v[2*d+1] + w1*(v[d+1] + v[3*d+1]) + w0*(v[1] + v[4*d+1]);
            float c2 = w2*v[2*d+2] + w1*(v[d+2] + v[3*d+2]) + w0*(v[2] + v[4*d+2]);
            float c3 = w2*v[2*d+3] + w1*(v[d+3] + v[3*d+3]) + w0*(v[3] + v[4*d+3]);
            int op = y * SP + x0 + SHIFT;
            bool center = (a == HL) ||
                          (y >= HL && y < S - HL && x0 >= HL && x0 < S - HL);
            if (center) {
                float4 prev = *reinterpret_cast<const float4*>(&P[op]);
                int gy = ty0 + y - HL;
                int gx = tx0 + x0 - HL;
                *reinterpret_cast<float4*>(&wch[gy * IMG + gx]) =
                    make_float4(prev.x - c0, prev.y - c1, prev.z - c2, prev.w - c3);
                if constexpr (LAST)
                    *reinterpret_cast<float4*>(&cch[gy * IMG + gx]) =
                        make_float4(c0, c1, c2, c3);
            }
            if constexpr (!LAST)
                *reinterpret_cast<float4*>(&P[op]) = make_float4(c0, c1, c2, c3);
        }
    }
}

__global__ void __launch_bounds__(NTHR, 3) uwt_kernel(const float* __restrict__ x,
                                                      float* __restrict__ out) {
    extern __shared__ float smem[];
    float* P = smem;
    float* Q = smem + S * SP + 4;

    const int b   = blockIdx.z;
    const int ty0 = blockIdx.y * TS;
    const int tx0 = blockIdx.x * TS;
    const float* xb = x + (size_t)b * IMG * IMG;
    float* ob = out + (size_t)b * 4 * IMG * IMG;

    // ---- level 1: H from gmem, W with gmem prev ----
    const bool interior = (tx0 >= 64 && tx0 <= IMG - TS - 16) &&
                          (ty0 >= 64 && ty0 <= IMG - TS - 16);
    if (interior) h1_pass<false>(xb, Q, ty0, tx0);
    else          h1_pass<true>(xb, Q, ty0, tx0);
    __syncthreads();
    w1_pass(P, Q, xb, ob + 0 * IMG * IMG, ty0, tx0);
    __syncthreads();

    // ---- levels 2, 3 ----
    do_level<2, 2, 6, false>(P, Q, ob + 1 * IMG * IMG, nullptr, ty0, tx0);
    __syncthreads();
    do_level<4, 6, 14, true>(P, Q, ob + 2 * IMG * IMG, ob + 3 * IMG * IMG,
                             ty0, tx0);
}

extern "C" void kernel_launch(void* const* d_in, const int* in_sizes, int n_in,
                              void* d_out, int out_size) {
    const float* x = (const float*)d_in[0];
    float* out     = (float*)d_out;

    cudaFuncSetAttribute(uwt_kernel, cudaFuncAttributeMaxDynamicSharedMemorySize,
                         (int)SMEM_BYTES);

    dim3 grid(IMG / TS, IMG / TS, 8);
    uwt_kernel<<<grid, NTHR, SMEM_BYTES>>>(x, out);
}